// round 12
// baseline (speedup 1.0000x reference)
#include <cuda_runtime.h>

// Problem constants (from reference)
#define NN 64
#define CC 256
#define EMBED 16
#define INDEX_K 16              // ceil(256^0.5) = 16
#define HW4 784                 // float4 per (n,c) slab (56*56/4)
#define SCALE (256.0f / 240.0f) // c / (c - INDEX)

// One block per (n,c) slab. NO block-wide barrier:
//  - warp 0 computes the full 256-channel rank in-warp (8 ch/lane) and
//    publishes (m, flag=blockIdx) through volatile smem.
//  - warps 1..7 front-batch their DRAM loads, spin on the smem flag (LDS,
//    block-local), then scale+store. Stale smem flag can never equal this
//    block's id within a launch; across replays a stale match delivers the
//    identical (call-invariant) m, so it is benign.
__global__ void __launch_bounds__(256)
fused_kernel(const float4* __restrict__ x,
             const float* __restrict__ embeds,
             const float* __restrict__ table,
             float4* __restrict__ out) {
    __shared__ volatile unsigned s_flag;
    __shared__ volatile float s_m;

    const int nc = blockIdx.x;
    const int n = nc >> 8;       // sample
    const int c = nc & 255;      // this block's channel
    const int t = threadIdx.x;
    const int wid = t >> 5;
    const int lane = t & 31;

    const long long base = (long long)nc * HW4;
    const float4* __restrict__ xin = x + base;
    float4* __restrict__ o = out + base;

    // ---- all warps: front-batch own DRAM loads (784 = 3*256 + 16) ----
    // tail handled by warp 7 (t in [240,256)) so warp 0 stays lean.
    const bool tail = (t >= 240);
    const int tidx = 768 + (t - 240);
    float4 v0 = xin[t];
    float4 v1 = xin[t + 256];
    float4 v2 = xin[t + 512];
    float4 v3;
    if (tail) v3 = xin[tidx];

    float m;
    if (wid == 0) {
        // ---- warp 0: full 256-channel rank, in-warp only ----
        float a0 = 0.f, a1 = 0.f, a2 = 0.f, a3 = 0.f;
        float a4 = 0.f, a5 = 0.f, a6 = 0.f, a7 = 0.f;
        const float4* __restrict__ tab4 = (const float4*)table;  // [16][64]
        const float* __restrict__ emb = embeds + n * EMBED;
#pragma unroll
        for (int e = 0; e < EMBED; ++e) {
            const float w = __ldg(emb + e);                   // uniform
            const float4 t0 = __ldg(tab4 + e * 64 + lane * 2);
            const float4 t1 = __ldg(tab4 + e * 64 + lane * 2 + 1);
            a0 += w * t0.x; a1 += w * t0.y; a2 += w * t0.z; a3 += w * t0.w;
            a4 += w * t1.x; a5 += w * t1.y; a6 += w * t1.z; a7 += w * t1.w;
        }
        // activ[c]: lane (c>>3), slot (c&7)
        const int ks = c & 7;
        float av = (ks == 0) ? a0 : (ks == 1) ? a1 : (ks == 2) ? a2 : (ks == 3) ? a3
                 : (ks == 4) ? a4 : (ks == 5) ? a5 : (ks == 6) ? a6 : a7;
        const float ac = __shfl_sync(0xffffffffu, av, c >> 3);
        // keep <=> #{j: activ[j] <= activ[c]} >= INDEX_K+1 (tie-safe)
        int cnt8 = (a0 <= ac) + (a1 <= ac) + (a2 <= ac) + (a3 <= ac)
                 + (a4 <= ac) + (a5 <= ac) + (a6 <= ac) + (a7 <= ac);
        const int cnt = __reduce_add_sync(0xffffffffu, cnt8);
        m = (cnt >= INDEX_K + 1) ? SCALE : 0.0f;
        if (lane == 0) {
            s_m = m;
            __threadfence_block();
            s_flag = (unsigned)nc;
        }
    } else {
        // ---- warps 1..7: spin on block-local smem flag ----
        while (s_flag != (unsigned)nc) { /* LDS poll, ~29 cyc */ }
        __threadfence_block();
        m = s_m;
    }

    // ---- scale + store (gated only by own loads + m) ----
    v0.x *= m; v0.y *= m; v0.z *= m; v0.w *= m;
    v1.x *= m; v1.y *= m; v1.z *= m; v1.w *= m;
    v2.x *= m; v2.y *= m; v2.z *= m; v2.w *= m;
    o[t]       = v0;
    o[t + 256] = v1;
    o[t + 512] = v2;
    if (tail) {
        v3.x *= m; v3.y *= m; v3.z *= m; v3.w *= m;
        o[tidx] = v3;
    }
}

extern "C" void kernel_launch(void* const* d_in, const int* in_sizes, int n_in,
                              void* d_out, int out_size) {
    const float* x      = (const float*)d_in[0];  // [64,256,56,56]
    const float* embeds = (const float*)d_in[1];  // [64,16]
    const float* table  = (const float*)d_in[2];  // [16,256]
    float* out = (float*)d_out;

    fused_kernel<<<NN * CC, 256>>>((const float4*)x, embeds, table, (float4*)out);
}

// round 13
// speedup vs baseline: 1.0969x; 1.0969x over previous
#include <cuda_runtime.h>

// Problem constants (from reference)
#define NN 64
#define CC 256
#define EMBED 16
#define INDEX_K 16              // ceil(256^0.5) = 16
#define HW4 784                 // float4 per (n,c) slab (56*56/4)
#define SCALE (256.0f / 240.0f) // c / (c - INDEX)

// One block per (n,c) slab. R11 ordering (mask loads -> barrier -> DRAM loads
// -> count-barrier -> stores), but the mask's table reads are vectorized:
// only threads 0..63 load, each computing 4 channels via LDG.128
// (32 warp-insts/block instead of 128 -> ~4x less LSU issue for the mask).
__global__ void __launch_bounds__(256)
fused_kernel(const float4* __restrict__ x,
             const float* __restrict__ embeds,
             const float* __restrict__ table,
             float4* __restrict__ out) {
    __shared__ float s_act[CC];

    const int nc = blockIdx.x;
    const int n = nc >> 8;       // sample
    const int c = nc & 255;      // this block's channel
    const int t = threadIdx.x;

    const long long base = (long long)nc * HW4;
    const float4* __restrict__ xin = x + base;
    float4* __restrict__ o = out + base;

    // ---- phase 1: threads 0..63 compute 4 channels each (float4 loads) ----
    if (t < 64) {
        const float4* __restrict__ tab4 = (const float4*)table;  // [16][64]
        const float* __restrict__ emb = embeds + n * EMBED;
        float ax = 0.f, ay = 0.f, az = 0.f, aw = 0.f;
#pragma unroll
        for (int e = 0; e < EMBED; ++e) {
            const float w = __ldg(emb + e);                 // uniform broadcast
            const float4 tv = __ldg(tab4 + e * 64 + t);     // L1-hot LDG.128
            ax += w * tv.x; ay += w * tv.y; az += w * tv.z; aw += w * tv.w;
        }
        float4 r; r.x = ax; r.y = ay; r.z = az; r.w = aw;
        ((float4*)s_act)[t] = r;
    }
    __syncthreads();
    const float a = s_act[t];
    const float ac = s_act[c];

    // ---- phase 2: front-batch the slab's DRAM loads (784 = 3*256 + 16) ----
    const bool tail = (t < 16);
    float4 v0 = xin[t];
    float4 v1 = xin[t + 256];
    float4 v2 = xin[t + 512];
    float4 v3;
    if (tail) v3 = xin[t + 768];

    // ---- phase 3: rank count; barrier overlaps in-flight DRAM loads ----
    // keep <=> #{j: activ[j] <= activ[c]} >= INDEX_K+1 (tie-safe == sorted[16] <= activ[c])
    const int cnt = __syncthreads_count(a <= ac);
    const float m = (cnt >= INDEX_K + 1) ? SCALE : 0.0f;

    // ---- phase 4: scale + store ----
    v0.x *= m; v0.y *= m; v0.z *= m; v0.w *= m;
    v1.x *= m; v1.y *= m; v1.z *= m; v1.w *= m;
    v2.x *= m; v2.y *= m; v2.z *= m; v2.w *= m;
    o[t]       = v0;
    o[t + 256] = v1;
    o[t + 512] = v2;
    if (tail) {
        v3.x *= m; v3.y *= m; v3.z *= m; v3.w *= m;
        o[t + 768] = v3;
    }
}

extern "C" void kernel_launch(void* const* d_in, const int* in_sizes, int n_in,
                              void* d_out, int out_size) {
    const float* x      = (const float*)d_in[0];  // [64,256,56,56]
    const float* embeds = (const float*)d_in[1];  // [64,16]
    const float* table  = (const float*)d_in[2];  // [16,256]
    float* out = (float*)d_out;

    fused_kernel<<<NN * CC, 256>>>((const float4*)x, embeds, table, (float4*)out);
}